// round 3
// baseline (speedup 1.0000x reference)
#include <cuda_runtime.h>
#include <cuda_bf16.h>

// Problem constants
#define BB 8
#define CC 256
#define HH 64
#define WW 64
#define EE 32
#define KK 8192
#define NN 32768      // B*H*W
#define HWW 4096      // H*W

#define NSPLIT 4
#define KCHUNK 2048   // KK / NSPLIT

#define DECAY 0.99f
#define ONE_MINUS_DECAY 0.01f
#define EPSI 1e-5f
#define BETA 0.25f

// Output layout (flattened tuple, f32)
#define OFF_ZQ   0
#define OFF_IDX  1048576
#define OFF_QL   1081344
#define OFF_EMB  1081345
#define OFF_CS   1343489
#define OFF_W    1351681

// Scratch (device globals — no allocation allowed)
__device__ float g_z[NN * EE];         // 4 MB: z_flat [N][E]
__device__ float g_en[KK * EE];        // 1 MB: normalized embedding
__device__ float g_counts[KK];
__device__ float g_dw[KK * EE];        // 1 MB
__device__ float g_pbest[NSPLIT * NN]; // split-K partial max values
__device__ int   g_pidx[NSPLIT * NN];  // split-K partial argmax
__device__ float g_qsum;
__device__ float g_nsum;

// ---- packed f32x2 helpers ----
__device__ __forceinline__ void fma2(unsigned long long& acc, unsigned long long a, unsigned long long b) {
    asm("fma.rn.f32x2 %0, %1, %2, %0;" : "+l"(acc) : "l"(a), "l"(b));
}
__device__ __forceinline__ float2 unpack2(unsigned long long v) {
    float2 r;
    asm("mov.b64 {%0, %1}, %2;" : "=f"(r.x), "=f"(r.y) : "l"(v));
    return r;
}

// ---------------- zero scratch ----------------
__global__ void zero_kernel() {
    int i = blockIdx.x * blockDim.x + threadIdx.x;
    int stride = gridDim.x * blockDim.x;
    for (int j = i; j < KK * EE; j += stride) g_dw[j] = 0.0f;
    for (int j = i; j < KK; j += stride) g_counts[j] = 0.0f;
    if (i == 0) { g_qsum = 0.0f; g_nsum = 0.0f; }
}

// ---------------- 1x1 conv: z[n][e] = sum_c x[b,c,p]*Wq[e,c] + bq[e] ----------------
__global__ __launch_bounds__(256) void proj_kernel(
    const float* __restrict__ x, const float* __restrict__ Wq, const float* __restrict__ bq)
{
    __shared__ float sW[EE * CC];   // [e][c] 32KB
    __shared__ float sx[CC * 16];   // [c][pix] 16KB
    const int t = threadIdx.x;
    const int n0 = blockIdx.x * 16;
    const int b = n0 >> 12;
    const int p0 = n0 & (HWW - 1);

    for (int i = t; i < EE * CC; i += 256) sW[i] = Wq[i];
    const float* xb = x + (size_t)b * CC * HWW + p0;
    #pragma unroll
    for (int j = 0; j < 16; j++) {
        int idx = j * 256 + t;
        int c = idx >> 4, pix = idx & 15;
        sx[idx] = xb[c * HWW + pix];
    }
    __syncthreads();

    const int pix = t & 15;
    const int e0 = (t >> 4) << 1;   // 2 e-values per thread
    float a0 = 0.0f, a1 = 0.0f;
    #pragma unroll 8
    for (int c = 0; c < CC; c++) {
        float xv = sx[c * 16 + pix];
        a0 = fmaf(xv, sW[(e0 + 0) * CC + c], a0);
        a1 = fmaf(xv, sW[(e0 + 1) * CC + c], a1);
    }
    float* zr = g_z + (size_t)(n0 + pix) * EE + e0;
    zr[0] = a0 + bq[e0];
    zr[1] = a1 + bq[e0 + 1];
}

// ---------------- normalize embedding rows ----------------
__global__ __launch_bounds__(256) void enorm_kernel(const float* __restrict__ emb) {
    int k = blockIdx.x * 8 + (threadIdx.x >> 5);
    int e = threadIdx.x & 31;
    float v = emb[k * EE + e];
    float s = v * v;
    #pragma unroll
    for (int o = 16; o; o >>= 1) s += __shfl_xor_sync(0xFFFFFFFFu, s, o);
    float nrm = fmaxf(sqrtf(s), 1e-12f);
    g_en[k * EE + e] = v / nrm;
}

// ---------------- argmax over K-split of dot(z, en_k), 2 pixels/thread ----------------
// grid = 64 pixel-tiles (512 px each) * NSPLIT. Each thread: pixels n0+t, n0+t+256.
// en streamed through 32KB shared chunks (256 codes); 8 LDS.128/code serve 2 pixels.
__global__ __launch_bounds__(256, 2) void argmax_kernel() {
    __shared__ ulonglong2 sE[256 * 8];   // 256 codes x 32 floats = 32KB
    const int t = threadIdx.x;
    const int tile = blockIdx.x & 63;
    const int split = blockIdx.x >> 6;
    const int nA = tile * 512 + t;
    const int nB = nA + 256;
    const int kbase = split * KCHUNK;

    // Load both z rows into packed f32x2 registers (natural adjacent-e pairs)
    unsigned long long zA[16], zB[16];
    {
        const ulonglong2* ra = reinterpret_cast<const ulonglong2*>(g_z + (size_t)nA * EE);
        const ulonglong2* rb = reinterpret_cast<const ulonglong2*>(g_z + (size_t)nB * EE);
        #pragma unroll
        for (int i = 0; i < 8; i++) {
            ulonglong2 va = ra[i]; zA[2 * i] = va.x; zA[2 * i + 1] = va.y;
            ulonglong2 vb = rb[i]; zB[2 * i] = vb.x; zB[2 * i + 1] = vb.y;
        }
    }

    float bestA = -3.0e38f, bestB = -3.0e38f;
    int idxA = 0, idxB = 0;

    for (int kc = 0; kc < KCHUNK; kc += 256) {
        __syncthreads();
        const ulonglong2* src = reinterpret_cast<const ulonglong2*>(g_en + (size_t)(kbase + kc) * EE);
        #pragma unroll
        for (int i = 0; i < 8; i++) sE[i * 256 + t] = src[i * 256 + t];
        __syncthreads();

        #pragma unroll 2
        for (int kk = 0; kk < 256; kk++) {
            const ulonglong2* er = &sE[kk * 8];
            unsigned long long a = 0ull, b = 0ull;
            #pragma unroll
            for (int j = 0; j < 8; j++) {
                ulonglong2 e2 = er[j];
                fma2(a, zA[2 * j],     e2.x);
                fma2(a, zA[2 * j + 1], e2.y);
                fma2(b, zB[2 * j],     e2.x);
                fma2(b, zB[2 * j + 1], e2.y);
            }
            float2 fa = unpack2(a);
            float2 fb = unpack2(b);
            float sA = fa.x + fa.y;
            float sB = fb.x + fb.y;
            int k = kbase + kc + kk;
            bool pA = sA > bestA;       // strict > keeps first max
            bool pB = sB > bestB;
            bestA = pA ? sA : bestA;  idxA = pA ? k : idxA;
            bestB = pB ? sB : bestB;  idxB = pB ? k : idxB;
        }
    }
    g_pbest[split * NN + nA] = bestA;  g_pidx[split * NN + nA] = idxA;
    g_pbest[split * NN + nB] = bestB;  g_pidx[split * NN + nB] = idxB;
}

// ---------------- merge splits + gather z_q, qloss partial, EMA scatter ----------------
__global__ __launch_bounds__(256) void gather_kernel(const float* __restrict__ emb, float* __restrict__ out) {
    const int t = threadIdx.x;
    const int n = blockIdx.x * 256 + t;

    // merge split-K partials (ascending split order, strict > => first-max semantics)
    float best = g_pbest[n];
    int idx = g_pidx[n];
    #pragma unroll
    for (int s = 1; s < NSPLIT; s++) {
        float v = g_pbest[s * NN + n];
        int id = g_pidx[s * NN + n];
        bool p = v > best;
        best = p ? v : best;
        idx = p ? id : idx;
    }

    const int b = n >> 12, p = n & (HWW - 1);

    float ev[EE];
    const float4* er = reinterpret_cast<const float4*>(emb + (size_t)idx * EE);
    #pragma unroll
    for (int i = 0; i < 8; i++) {
        float4 v = er[i];
        ev[4 * i] = v.x; ev[4 * i + 1] = v.y; ev[4 * i + 2] = v.z; ev[4 * i + 3] = v.w;
    }

    const float* zrow = g_z + (size_t)n * EE;
    float* dwr = g_dw + (size_t)idx * EE;
    float sq = 0.0f;
    #pragma unroll
    for (int e = 0; e < EE; e++) {
        float zv = zrow[e];
        float d = ev[e] - zv;
        sq = fmaf(d, d, sq);
        atomicAdd(&dwr[e], zv);
    }
    atomicAdd(&g_counts[idx], 1.0f);

    // z_q_st (numerically == z_q = embedding[idx]) in [B,E,H,W] layout; coalesced across p
    float* ob = out + OFF_ZQ + (size_t)b * EE * HWW + p;
    #pragma unroll
    for (int e = 0; e < EE; e++) ob[(size_t)e * HWW] = ev[e];

    out[OFF_IDX + n] = (float)idx;

    __shared__ float red[256];
    red[t] = sq;
    __syncthreads();
    #pragma unroll
    for (int s = 128; s; s >>= 1) {
        if (t < s) red[t] += red[t + s];
        __syncthreads();
    }
    if (t == 0) atomicAdd(&g_qsum, red[0]);
}

// ---------------- EMA stage 1: new_cs + total n ----------------
__global__ __launch_bounds__(256) void ema1_kernel(const float* __restrict__ ema_cs, float* __restrict__ out) {
    const int t = threadIdx.x;
    const int k = blockIdx.x * 256 + t;
    float c = DECAY * ema_cs[k] + ONE_MINUS_DECAY * g_counts[k];
    out[OFF_CS + k] = c;
    __shared__ float red[256];
    red[t] = c;
    __syncthreads();
    #pragma unroll
    for (int s = 128; s; s >>= 1) {
        if (t < s) red[t] += red[t + s];
        __syncthreads();
    }
    if (t == 0) atomicAdd(&g_nsum, red[0]);
}

// ---------------- EMA stage 2: new_w, new_embedding, qloss ----------------
__global__ __launch_bounds__(256) void ema2_kernel(const float* __restrict__ ema_w, float* __restrict__ out) {
    const int i = blockIdx.x * 256 + threadIdx.x;   // over K*E
    const int k = i >> 5;
    float w = DECAY * ema_w[i] + ONE_MINUS_DECAY * g_dw[i];
    out[OFF_W + i] = w;
    float nt = g_nsum;
    float c = out[OFF_CS + k];
    float cs = (c + EPSI) / (nt + (float)KK * EPSI) * nt;
    out[OFF_EMB + i] = w / cs;
    if (i == 0) out[OFF_QL] = BETA * g_qsum / (float)(NN * EE);
}

extern "C" void kernel_launch(void* const* d_in, const int* in_sizes, int n_in,
                              void* d_out, int out_size) {
    const float* x   = (const float*)d_in[0];
    const float* Wq  = (const float*)d_in[1];
    const float* bq  = (const float*)d_in[2];
    const float* emb = (const float*)d_in[3];
    const float* ecs = (const float*)d_in[4];
    const float* ew  = (const float*)d_in[5];
    float* out = (float*)d_out;

    zero_kernel<<<264, 512>>>();
    proj_kernel<<<NN / 16, 256>>>(x, Wq, bq);
    enorm_kernel<<<KK / 8, 256>>>(emb);
    argmax_kernel<<<64 * NSPLIT, 256>>>();
    gather_kernel<<<NN / 256, 256>>>(emb, out);
    ema1_kernel<<<KK / 256, 256>>>(ecs, out);
    ema2_kernel<<<(KK * EE) / 256, 256>>>(ew, out);
}

// round 9
// speedup vs baseline: 1.1323x; 1.1323x over previous
#include <cuda_runtime.h>
#include <cuda_fp16.h>
#include <cstdint>
#include <cfloat>

#define CC 256
#define EE 32
#define KK 8192
#define NN 32768
#define HWW 4096
#define NTILES 64        // KK / 128

#define DECAY 0.99f
#define ONE_MINUS_DECAY 0.01f
#define EPSI 1e-5f
#define BETA 0.25f

#define OFF_ZQ   0
#define OFF_IDX  1048576
#define OFF_QL   1081344
#define OFF_EMB  1081345
#define OFF_CS   1343489
#define OFF_W    1351681

// Scratch (device globals)
__device__ float g_z[NN * EE];                    // fp32 z_flat
__device__ __align__(16) __half g_bh[KK * 128];   // 2MB: per code row, 128 f16 = [eh|eh|el|el]
__device__ float g_inorm[KK];
__device__ float g_counts[KK];
__device__ float g_dw[KK * EE];
__device__ int   g_bidx[NN];
__device__ float g_qsum;
__device__ float g_nsum;

// ---------------- helpers ----------------
__device__ __forceinline__ uint32_t smem_u32(const void* p) {
    uint32_t a;
    asm("{ .reg .u64 t; cvta.to.shared.u64 t, %1; cvt.u32.u64 %0, t; }" : "=r"(a) : "l"(p));
    return a;
}
__device__ __forceinline__ void mma16816(float* c, const uint32_t* a, const uint32_t* b) {
    asm volatile("mma.sync.aligned.m16n8k16.row.col.f32.f16.f16.f32 "
        "{%0,%1,%2,%3}, {%4,%5,%6,%7}, {%8,%9}, {%0,%1,%2,%3};"
        : "+f"(c[0]), "+f"(c[1]), "+f"(c[2]), "+f"(c[3])
        : "r"(a[0]), "r"(a[1]), "r"(a[2]), "r"(a[3]), "r"(b[0]), "r"(b[1]));
}
__device__ __forceinline__ void ldsm4(uint32_t* r, uint32_t addr) {
    asm volatile("ldmatrix.sync.aligned.m8n8.x4.shared.b16 {%0,%1,%2,%3}, [%4];"
        : "=r"(r[0]), "=r"(r[1]), "=r"(r[2]), "=r"(r[3]) : "r"(addr));
}
__device__ __forceinline__ void ldsm2(uint32_t* r, uint32_t addr) {
    asm volatile("ldmatrix.sync.aligned.m8n8.x2.shared.b16 {%0,%1}, [%2];"
        : "=r"(r[0]), "=r"(r[1]) : "r"(addr));
}
// XOR swizzle: rows of 256B, permute 16B chunks within each 128B half by row&7
__device__ __forceinline__ int swz(int row, int byte_) {
    int c8 = byte_ >> 4;
    int c8s = (c8 & 8) | ((c8 ^ row) & 7);
    return row * 256 + (c8s << 4) + (byte_ & 15);
}

// ---------------- zero ----------------
__global__ void zero_kernel() {
    int i = blockIdx.x * blockDim.x + threadIdx.x;
    int stride = gridDim.x * blockDim.x;
    for (int j = i; j < KK * EE; j += stride) g_dw[j] = 0.0f;
    for (int j = i; j < KK; j += stride) g_counts[j] = 0.0f;
    if (i == 0) { g_qsum = 0.0f; g_nsum = 0.0f; }
}

// ---------------- 1x1 conv ----------------
__global__ __launch_bounds__(256) void proj_kernel(
    const float* __restrict__ x, const float* __restrict__ Wq, const float* __restrict__ bq)
{
    __shared__ float sW[EE * CC];
    __shared__ float sx[CC * 16];
    const int t = threadIdx.x;
    const int n0 = blockIdx.x * 16;
    const int b = n0 >> 12;
    const int p0 = n0 & (HWW - 1);

    for (int i = t; i < EE * CC; i += 256) sW[i] = Wq[i];
    const float* xb = x + (size_t)b * CC * HWW + p0;
    #pragma unroll
    for (int j = 0; j < 16; j++) {
        int idx = j * 256 + t;
        int c = idx >> 4, pix = idx & 15;
        sx[idx] = xb[c * HWW + pix];
    }
    __syncthreads();

    const int pix = t & 15;
    const int e0 = (t >> 4) << 1;
    float a0 = 0.0f, a1 = 0.0f;
    #pragma unroll 8
    for (int c = 0; c < CC; c++) {
        float xv = sx[c * 16 + pix];
        a0 = fmaf(xv, sW[(e0 + 0) * CC + c], a0);
        a1 = fmaf(xv, sW[(e0 + 1) * CC + c], a1);
    }
    float* zr = g_z + (size_t)(n0 + pix) * EE + e0;
    zr[0] = a0 + bq[e0];
    zr[1] = a1 + bq[e0 + 1];
}

// ---------------- embedding inverse norms (scaled by 256) ----------------
__global__ __launch_bounds__(256) void inorm_kernel(const float* __restrict__ emb) {
    int k = blockIdx.x * 8 + (threadIdx.x >> 5);
    int e = threadIdx.x & 31;
    float v = emb[k * EE + e];
    float s = v * v;
    #pragma unroll
    for (int o = 16; o; o >>= 1) s += __shfl_xor_sync(0xFFFFFFFFu, s, o);
    if (e == 0) g_inorm[k] = 256.0f / fmaxf(sqrtf(s), 1e-12f);
}

// ---------------- pack B: natural row-major [code][128] = [eh|eh|el|el] ----------------
__global__ __launch_bounds__(256) void pack_bh_kernel(const float* __restrict__ emb) {
    const int code = blockIdx.x * 16 + (threadIdx.x >> 4);
    const int e0 = (threadIdx.x & 15) * 2;
    const float inv = g_inorm[code];
    float v0 = emb[(size_t)code * EE + e0] * inv;
    float v1 = emb[(size_t)code * EE + e0 + 1] * inv;
    __half h0 = __float2half_rn(v0), h1 = __float2half_rn(v1);
    __half l0 = __float2half_rn(v0 - __half2float(h0));
    __half l1 = __float2half_rn(v1 - __half2float(h1));
    __half2 hh = __halves2half2(h0, h1);
    __half2 ll = __halves2half2(l0, l1);
    __half2* row = (__half2*)(g_bh + (size_t)code * 128);
    const int i2 = e0 >> 1;
    row[i2]      = hh;   // k in [0,32)
    row[i2 + 16] = hh;   // k in [32,64)
    row[i2 + 32] = ll;   // k in [64,96)
    row[i2 + 48] = ll;   // k in [96,128)
}

// ---------------- HMMA argmax: smem score round-trip ----------------
// 256 CTAs x 256 thr (8 warps, 4m x 2n). M=128 pixels/CTA, 64 tiles of 128 codes, K=128.
// SMEM: A 32KB @0, B 32KB @32768, scores 128x132 fp32 @65536. Total 133120 B.
#define SC_PITCH 132
#define SMEM_TOTAL (65536 + 128 * SC_PITCH * 4)

__global__ __launch_bounds__(256) void argmax_hmma_kernel() {
    extern __shared__ __align__(16) char smem[];
    char* smA = smem;
    char* smB = smem + 32768;
    float* scores = (float*)(smem + 65536);
    const int t = threadIdx.x;
    const int l = t & 31, wid = t >> 5;
    const int wm = wid & 3, wn = wid >> 2;
    const int blk = blockIdx.x;
    const uint32_t sbA = smem_u32(smA);
    const uint32_t sbB = smem_u32(smB);

    // ---- build A tile: pixel rows, K=128 = [zh|zl|zh|zl], swizzled ----
    {
        const int row = t >> 1;
        const int e0 = (t & 1) * 16;
        const float4* zr = (const float4*)(g_z + (size_t)(blk * 128 + row) * EE + e0);
        float zf[16];
        #pragma unroll
        for (int i = 0; i < 4; i++) {
            float4 v = zr[i];
            zf[4 * i] = v.x; zf[4 * i + 1] = v.y; zf[4 * i + 2] = v.z; zf[4 * i + 3] = v.w;
        }
        #pragma unroll
        for (int i = 0; i < 16; i += 2) {
            float v0 = 256.0f * zf[i];
            float v1 = 256.0f * zf[i + 1];
            __half h0 = __float2half_rn(v0), h1 = __float2half_rn(v1);
            __half l0 = __float2half_rn(v0 - __half2float(h0));
            __half l1 = __float2half_rn(v1 - __half2float(h1));
            __half2 hh = __halves2half2(h0, h1);
            __half2 ll = __halves2half2(l0, l1);
            const int b0 = 2 * (e0 + i);
            *(__half2*)(smA + swz(row, b0))       = hh;   // k = e
            *(__half2*)(smA + swz(row, b0 + 64))  = ll;   // k = e+32
            *(__half2*)(smA + swz(row, b0 + 128)) = hh;   // k = e+64
            *(__half2*)(smA + swz(row, b0 + 192)) = ll;   // k = e+96
        }
    }

    float best = -FLT_MAX;
    int bidx = 0;

    // ldmatrix lane addressing pieces
    const int arow0 = wm * 32 + (l & 15);
    const int abyte_lane = ((l >> 4) & 1) * 16;
    const int brow_lane = (l & 7);
    const int bbyte_lane = ((l >> 3) & 1) * 16;

    // scan assignment: thread t owns row t>>1, column half t&1
    const float* srow = scores + (t >> 1) * SC_PITCH + (t & 1) * 64;

    for (int tt = 0; tt < NTILES; tt++) {
        __syncthreads();   // previous tile's scan done; A build done (tt=0)
        // ---- copy B tile (codes tt*128..+127), swizzled ----
        const uint4* src = (const uint4*)(g_bh + (size_t)tt * 128 * 128);
        #pragma unroll
        for (int i = 0; i < 8; i++) {
            int c = t + i * 256;
            int row = c >> 4, c8 = c & 15;
            uint4 v = src[c];
            int c8s = (c8 & 8) | ((c8 ^ row) & 7);
            *(uint4*)(smB + row * 256 + (c8s << 4)) = v;
        }
        __syncthreads();

        // ---- compute 128x128 scores ----
        float c_[2][8][4];
        #pragma unroll
        for (int mi = 0; mi < 2; mi++)
            #pragma unroll
            for (int j = 0; j < 8; j++)
                #pragma unroll
                for (int q = 0; q < 4; q++) c_[mi][j][q] = 0.0f;

        #pragma unroll
        for (int s = 0; s < 8; s++) {
            uint32_t a0[4], a1[4];
            const int abyte = s * 32 + abyte_lane;
            ldsm4(a0, sbA + swz(arow0, abyte));
            ldsm4(a1, sbA + swz(arow0 + 16, abyte));
            #pragma unroll
            for (int j = 0; j < 8; j++) {
                uint32_t b[2];
                const int brow = (wn * 8 + j) * 8 + brow_lane;
                ldsm2(b, sbB + swz(brow, s * 32 + bbyte_lane));
                mma16816(c_[0][j], a0, b);
                mma16816(c_[1][j], a1, b);
            }
        }

        // ---- store C fragments to smem scores (claimed C mapping) ----
        #pragma unroll
        for (int mi = 0; mi < 2; mi++) {
            const int r0 = wm * 32 + mi * 16 + (l >> 2);
            #pragma unroll
            for (int j = 0; j < 8; j++) {
                const int col = wn * 64 + j * 8 + (l & 3) * 2;
                float* p0 = scores + r0 * SC_PITCH + col;
                float* p1 = scores + (r0 + 8) * SC_PITCH + col;
                p0[0] = c_[mi][j][0];
                p0[1] = c_[mi][j][1];
                p1[0] = c_[mi][j][2];
                p1[1] = c_[mi][j][3];
            }
        }
        __syncthreads();

        // ---- trivially-correct serial scan: ascending col, strict > ----
        const int cb = tt * 128 + (t & 1) * 64;
        #pragma unroll 4
        for (int c = 0; c < 64; c += 4) {
            float4 v = *(const float4*)(srow + c);
            if (v.x > best) { best = v.x; bidx = cb + c; }
            if (v.y > best) { best = v.y; bidx = cb + c + 1; }
            if (v.z > best) { best = v.z; bidx = cb + c + 2; }
            if (v.w > best) { best = v.w; bidx = cb + c + 3; }
        }
    }

    // merge the two column halves of each row (adjacent threads = adjacent lanes)
    {
        float ov = __shfl_xor_sync(0xFFFFFFFFu, best, 1);
        int oi = __shfl_xor_sync(0xFFFFFFFFu, bidx, 1);
        if (ov > best || (ov == best && oi < bidx)) { best = ov; bidx = oi; }
        if ((t & 1) == 0) g_bidx[blk * 128 + (t >> 1)] = bidx;
    }
}

// ---------------- gather + qloss + EMA scatter ----------------
__global__ __launch_bounds__(256) void gather_kernel(const float* __restrict__ emb, float* __restrict__ out) {
    const int t = threadIdx.x;
    const int n = blockIdx.x * 256 + t;
    const int idx = g_bidx[n];
    const int b = n >> 12, p = n & (HWW - 1);

    float ev[EE];
    const float4* er = reinterpret_cast<const float4*>(emb + (size_t)idx * EE);
    #pragma unroll
    for (int i = 0; i < 8; i++) {
        float4 v = er[i];
        ev[4 * i] = v.x; ev[4 * i + 1] = v.y; ev[4 * i + 2] = v.z; ev[4 * i + 3] = v.w;
    }

    const float* zrow = g_z + (size_t)n * EE;
    float* dwr = g_dw + (size_t)idx * EE;
    float sq = 0.0f;
    #pragma unroll
    for (int e = 0; e < EE; e++) {
        float zv = zrow[e];
        float d = ev[e] - zv;
        sq = fmaf(d, d, sq);
        atomicAdd(&dwr[e], zv);
    }
    atomicAdd(&g_counts[idx], 1.0f);

    float* ob = out + OFF_ZQ + (size_t)b * EE * HWW + p;
    #pragma unroll
    for (int e = 0; e < EE; e++) ob[(size_t)e * HWW] = ev[e];

    out[OFF_IDX + n] = (float)idx;

    __shared__ float red[256];
    red[t] = sq;
    __syncthreads();
    #pragma unroll
    for (int s = 128; s; s >>= 1) {
        if (t < s) red[t] += red[t + s];
        __syncthreads();
    }
    if (t == 0) atomicAdd(&g_qsum, red[0]);
}

__global__ __launch_bounds__(256) void ema1_kernel(const float* __restrict__ ema_cs, float* __restrict__ out) {
    const int t = threadIdx.x;
    const int k = blockIdx.x * 256 + t;
    float c = DECAY * ema_cs[k] + ONE_MINUS_DECAY * g_counts[k];
    out[OFF_CS + k] = c;
    __shared__ float red[256];
    red[t] = c;
    __syncthreads();
    #pragma unroll
    for (int s = 128; s; s >>= 1) {
        if (t < s) red[t] += red[t + s];
        __syncthreads();
    }
    if (t == 0) atomicAdd(&g_nsum, red[0]);
}

__global__ __launch_bounds__(256) void ema2_kernel(const float* __restrict__ ema_w, float* __restrict__ out) {
    const int i = blockIdx.x * 256 + threadIdx.x;
    const int k = i >> 5;
    float w = DECAY * ema_w[i] + ONE_MINUS_DECAY * g_dw[i];
    out[OFF_W + i] = w;
    float nt = g_nsum;
    float c = out[OFF_CS + k];
    float cs = (c + EPSI) / (nt + (float)KK * EPSI) * nt;
    out[OFF_EMB + i] = w / cs;
    if (i == 0) out[OFF_QL] = BETA * g_qsum / (float)(NN * EE);
}

extern "C" void kernel_launch(void* const* d_in, const int* in_sizes, int n_in,
                              void* d_out, int out_size) {
    const float* x   = (const float*)d_in[0];
    const float* Wq  = (const float*)d_in[1];
    const float* bq  = (const float*)d_in[2];
    const float* emb = (const float*)d_in[3];
    const float* ecs = (const float*)d_in[4];
    const float* ew  = (const float*)d_in[5];
    float* out = (float*)d_out;

    cudaFuncSetAttribute(argmax_hmma_kernel, cudaFuncAttributeMaxDynamicSharedMemorySize, SMEM_TOTAL);

    zero_kernel<<<264, 512>>>();
    proj_kernel<<<NN / 16, 256>>>(x, Wq, bq);
    inorm_kernel<<<KK / 8, 256>>>(emb);
    pack_bh_kernel<<<KK / 16, 256>>>(emb);
    argmax_hmma_kernel<<<256, 256, SMEM_TOTAL>>>();
    gather_kernel<<<NN / 256, 256>>>(emb, out);
    ema1_kernel<<<KK / 256, 256>>>(ecs, out);
    ema2_kernel<<<(KK * EE) / 256, 256>>>(ew, out);
}

// round 10
// speedup vs baseline: 1.2883x; 1.1378x over previous
#include <cuda_runtime.h>
#include <cuda_fp16.h>
#include <cstdint>
#include <cfloat>

#define CC 256
#define EE 32
#define KK 8192
#define NN 32768
#define HWW 4096
#define NT2 128          // tiles of 64 codes

#define DECAY 0.99f
#define ONE_MINUS_DECAY 0.01f
#define EPSI 1e-5f
#define BETA 0.25f

#define OFF_ZQ   0
#define OFF_IDX  1048576
#define OFF_QL   1081344
#define OFF_EMB  1081345
#define OFF_CS   1343489
#define OFF_W    1351681

// Scratch (device globals)
__device__ float g_z[NN * EE];                    // fp32 z_flat
__device__ __align__(16) __half g_bh[KK * 128];   // 2MB: per code row, 128 f16 = [eh|eh|el|el]
__device__ float g_inorm[KK];
__device__ float g_counts[KK];
__device__ float g_dw[KK * EE];
__device__ int   g_bidx[NN];
__device__ float g_qsum;
__device__ float g_nsum;

// ---------------- helpers ----------------
__device__ __forceinline__ uint32_t smem_u32(const void* p) {
    uint32_t a;
    asm("{ .reg .u64 t; cvta.to.shared.u64 t, %1; cvt.u32.u64 %0, t; }" : "=r"(a) : "l"(p));
    return a;
}
__device__ __forceinline__ void cp_async16(uint32_t saddr, const void* gaddr) {
    asm volatile("cp.async.cg.shared.global [%0], [%1], 16;" :: "r"(saddr), "l"(gaddr) : "memory");
}
__device__ __forceinline__ void mma16816(float* c, const uint32_t* a, const uint32_t* b) {
    asm volatile("mma.sync.aligned.m16n8k16.row.col.f32.f16.f16.f32 "
        "{%0,%1,%2,%3}, {%4,%5,%6,%7}, {%8,%9}, {%0,%1,%2,%3};"
        : "+f"(c[0]), "+f"(c[1]), "+f"(c[2]), "+f"(c[3])
        : "r"(a[0]), "r"(a[1]), "r"(a[2]), "r"(a[3]), "r"(b[0]), "r"(b[1]));
}
__device__ __forceinline__ void ldsm4(uint32_t* r, uint32_t addr) {
    asm volatile("ldmatrix.sync.aligned.m8n8.x4.shared.b16 {%0,%1,%2,%3}, [%4];"
        : "=r"(r[0]), "=r"(r[1]), "=r"(r[2]), "=r"(r[3]) : "r"(addr));
}
__device__ __forceinline__ void ldsm2(uint32_t* r, uint32_t addr) {
    asm volatile("ldmatrix.sync.aligned.m8n8.x2.shared.b16 {%0,%1}, [%2];"
        : "=r"(r[0]), "=r"(r[1]) : "r"(addr));
}
// XOR swizzle: rows of 256B, permute 16B chunks within each 128B half by row&7
__device__ __forceinline__ int swz(int row, int byte_) {
    int c8 = byte_ >> 4;
    int c8s = (c8 & 8) | ((c8 ^ row) & 7);
    return row * 256 + (c8s << 4) + (byte_ & 15);
}

// ---------------- zero ----------------
__global__ void zero_kernel() {
    int i = blockIdx.x * blockDim.x + threadIdx.x;
    int stride = gridDim.x * blockDim.x;
    for (int j = i; j < KK * EE; j += stride) g_dw[j] = 0.0f;
    for (int j = i; j < KK; j += stride) g_counts[j] = 0.0f;
    if (i == 0) { g_qsum = 0.0f; g_nsum = 0.0f; }
}

// ---------------- 1x1 conv ----------------
__global__ __launch_bounds__(256) void proj_kernel(
    const float* __restrict__ x, const float* __restrict__ Wq, const float* __restrict__ bq)
{
    __shared__ float sW[EE * CC];
    __shared__ float sx[CC * 16];
    const int t = threadIdx.x;
    const int n0 = blockIdx.x * 16;
    const int b = n0 >> 12;
    const int p0 = n0 & (HWW - 1);

    for (int i = t; i < EE * CC; i += 256) sW[i] = Wq[i];
    const float* xb = x + (size_t)b * CC * HWW + p0;
    #pragma unroll
    for (int j = 0; j < 16; j++) {
        int idx = j * 256 + t;
        int c = idx >> 4, pix = idx & 15;
        sx[idx] = xb[c * HWW + pix];
    }
    __syncthreads();

    const int pix = t & 15;
    const int e0 = (t >> 4) << 1;
    float a0 = 0.0f, a1 = 0.0f;
    #pragma unroll 8
    for (int c = 0; c < CC; c++) {
        float xv = sx[c * 16 + pix];
        a0 = fmaf(xv, sW[(e0 + 0) * CC + c], a0);
        a1 = fmaf(xv, sW[(e0 + 1) * CC + c], a1);
    }
    float* zr = g_z + (size_t)(n0 + pix) * EE + e0;
    zr[0] = a0 + bq[e0];
    zr[1] = a1 + bq[e0 + 1];
}

// ---------------- embedding inverse norms (scaled by 256) ----------------
__global__ __launch_bounds__(256) void inorm_kernel(const float* __restrict__ emb) {
    int k = blockIdx.x * 8 + (threadIdx.x >> 5);
    int e = threadIdx.x & 31;
    float v = emb[k * EE + e];
    float s = v * v;
    #pragma unroll
    for (int o = 16; o; o >>= 1) s += __shfl_xor_sync(0xFFFFFFFFu, s, o);
    if (e == 0) g_inorm[k] = 256.0f / fmaxf(sqrtf(s), 1e-12f);
}

// ---------------- pack B: natural row-major [code][128] = [eh|eh|el|el] ----------------
__global__ __launch_bounds__(256) void pack_bh_kernel(const float* __restrict__ emb) {
    const int code = blockIdx.x * 16 + (threadIdx.x >> 4);
    const int e0 = (threadIdx.x & 15) * 2;
    const float inv = g_inorm[code];
    float v0 = emb[(size_t)code * EE + e0] * inv;
    float v1 = emb[(size_t)code * EE + e0 + 1] * inv;
    __half h0 = __float2half_rn(v0), h1 = __float2half_rn(v1);
    __half l0 = __float2half_rn(v0 - __half2float(h0));
    __half l1 = __float2half_rn(v1 - __half2float(h1));
    __half2 hh = __halves2half2(h0, h1);
    __half2 ll = __halves2half2(l0, l1);
    __half2* row = (__half2*)(g_bh + (size_t)code * 128);
    const int i2 = e0 >> 1;
    row[i2]      = hh;   // k in [0,32)
    row[i2 + 16] = hh;   // k in [32,64)
    row[i2 + 32] = ll;   // k in [64,96)
    row[i2 + 48] = ll;   // k in [96,128)
}

// ---------------- HMMA argmax: 64-code tiles, cp.async double-buffer, smem scores ----------------
// 256 CTAs x 256 thr (8 warps, 4m x 2n). M=128 pixels/CTA, 128 tiles of 64 codes, K=128.
// SMEM: A 32KB @0, B0 16KB @32768, B1 16KB @49152, scores 128x68 fp32 @65536.
#define SC_PITCH 68
#define SMEM_TOTAL (65536 + 128 * SC_PITCH * 4)   // 100352 -> 2 CTAs/SM

__global__ __launch_bounds__(256, 2) void argmax_hmma_kernel() {
    extern __shared__ __align__(16) char smem[];
    char* smA = smem;
    float* scores = (float*)(smem + 65536);
    const int t = threadIdx.x;
    const int l = t & 31, wid = t >> 5;
    const int wm = wid & 3, wn = wid >> 2;
    const int blk = blockIdx.x;
    const uint32_t sbA = smem_u32(smA);
    const uint32_t sbB = sbA + 32768;

    // ---- build A tile: pixel rows, K=128 = [zh|zl|zh|zl], swizzled ----
    {
        const int row = t >> 1;
        const int e0 = (t & 1) * 16;
        const float4* zr = (const float4*)(g_z + (size_t)(blk * 128 + row) * EE + e0);
        float zf[16];
        #pragma unroll
        for (int i = 0; i < 4; i++) {
            float4 v = zr[i];
            zf[4 * i] = v.x; zf[4 * i + 1] = v.y; zf[4 * i + 2] = v.z; zf[4 * i + 3] = v.w;
        }
        #pragma unroll
        for (int i = 0; i < 16; i += 2) {
            float v0 = 256.0f * zf[i];
            float v1 = 256.0f * zf[i + 1];
            __half h0 = __float2half_rn(v0), h1 = __float2half_rn(v1);
            __half l0 = __float2half_rn(v0 - __half2float(h0));
            __half l1 = __float2half_rn(v1 - __half2float(h1));
            __half2 hh = __halves2half2(h0, h1);
            __half2 ll = __halves2half2(l0, l1);
            const int b0 = 2 * (e0 + i);
            *(__half2*)(smA + swz(row, b0))       = hh;   // k = e
            *(__half2*)(smA + swz(row, b0 + 64))  = ll;   // k = e+32
            *(__half2*)(smA + swz(row, b0 + 128)) = hh;   // k = e+64
            *(__half2*)(smA + swz(row, b0 + 192)) = ll;   // k = e+96
        }
    }

    // ---- prologue: async-load B tile 0 ----
    // tile = 64 codes x 256B = 16KB; 256 threads x 16B x 4 iters; swizzled dst
    {
        const uint4* src = (const uint4*)g_bh;
        #pragma unroll
        for (int i = 0; i < 4; i++) {
            int c = t + i * 256;
            int row = c >> 4, c8 = c & 15;
            int c8s = (c8 & 8) | ((c8 ^ row) & 7);
            cp_async16(sbB + row * 256 + (c8s << 4), src + c);
        }
        asm volatile("cp.async.commit_group;" ::: "memory");
    }

    float best = -FLT_MAX;
    int bidx = 0;

    // ldmatrix lane addressing pieces
    const int arow0 = wm * 32 + (l & 15);
    const int abyte_lane = ((l >> 4) & 1) * 16;
    const int brow_lane = (l & 7);
    const int bbyte_lane = ((l >> 3) & 1) * 16;

    // scan assignment: thread t owns row t>>1, column half t&1 (32 cols)
    const float* srow = scores + (t >> 1) * SC_PITCH + (t & 1) * 32;

    for (int tt = 0; tt < NT2; tt++) {
        // issue prefetch of tile tt+1 into the other buffer (safe: MMA tt-1 fully done
        // before this point for all threads via the post-store sync of tt-1)
        if (tt + 1 < NT2) {
            const uint4* src = (const uint4*)(g_bh + (size_t)(tt + 1) * 64 * 128);
            uint32_t dst = sbB + ((tt + 1) & 1) * 16384;
            #pragma unroll
            for (int i = 0; i < 4; i++) {
                int c = t + i * 256;
                int row = c >> 4, c8 = c & 15;
                int c8s = (c8 & 8) | ((c8 ^ row) & 7);
                cp_async16(dst + row * 256 + (c8s << 4), src + c);
            }
        }
        asm volatile("cp.async.commit_group;" ::: "memory");
        asm volatile("cp.async.wait_group 1;" ::: "memory");   // B(tt) complete
        __syncthreads();   // B(tt) visible to all; scan(tt-1) done before store(tt)

        const uint32_t sB = sbB + (tt & 1) * 16384;

        // ---- compute 128x64 scores ----
        float c_[2][4][4];
        #pragma unroll
        for (int mi = 0; mi < 2; mi++)
            #pragma unroll
            for (int j = 0; j < 4; j++)
                #pragma unroll
                for (int q = 0; q < 4; q++) c_[mi][j][q] = 0.0f;

        #pragma unroll
        for (int s = 0; s < 8; s++) {
            uint32_t a0[4], a1[4];
            const int abyte = s * 32 + abyte_lane;
            ldsm4(a0, sbA + swz(arow0, abyte));
            ldsm4(a1, sbA + swz(arow0 + 16, abyte));
            #pragma unroll
            for (int j = 0; j < 4; j++) {
                uint32_t b[2];
                const int brow = (wn * 4 + j) * 8 + brow_lane;
                ldsm2(b, sB + swz(brow, s * 32 + bbyte_lane));
                mma16816(c_[0][j], a0, b);
                mma16816(c_[1][j], a1, b);
            }
        }

        // ---- store C fragments to smem scores (validated mapping) ----
        #pragma unroll
        for (int mi = 0; mi < 2; mi++) {
            const int r0 = wm * 32 + mi * 16 + (l >> 2);
            #pragma unroll
            for (int j = 0; j < 4; j++) {
                const int col = wn * 32 + j * 8 + (l & 3) * 2;
                float* p0 = scores + r0 * SC_PITCH + col;
                float* p1 = scores + (r0 + 8) * SC_PITCH + col;
                p0[0] = c_[mi][j][0];
                p0[1] = c_[mi][j][1];
                p1[0] = c_[mi][j][2];
                p1[1] = c_[mi][j][3];
            }
        }
        __syncthreads();

        // ---- serial scan: ascending col, strict > ----
        const int cb = tt * 64 + (t & 1) * 32;
        #pragma unroll
        for (int c = 0; c < 32; c += 4) {
            float4 v = *(const float4*)(srow + c);
            if (v.x > best) { best = v.x; bidx = cb + c; }
            if (v.y > best) { best = v.y; bidx = cb + c + 1; }
            if (v.z > best) { best = v.z; bidx = cb + c + 2; }
            if (v.w > best) { best = v.w; bidx = cb + c + 3; }
        }
    }

    // merge the two column halves of each row
    {
        float ov = __shfl_xor_sync(0xFFFFFFFFu, best, 1);
        int oi = __shfl_xor_sync(0xFFFFFFFFu, bidx, 1);
        if (ov > best || (ov == best && oi < bidx)) { best = ov; bidx = oi; }
        if ((t & 1) == 0) g_bidx[blk * 128 + (t >> 1)] = bidx;
    }
}

// ---------------- gather + qloss + EMA scatter ----------------
__global__ __launch_bounds__(256) void gather_kernel(const float* __restrict__ emb, float* __restrict__ out) {
    const int t = threadIdx.x;
    const int n = blockIdx.x * 256 + t;
    const int idx = g_bidx[n];
    const int b = n >> 12, p = n & (HWW - 1);

    float ev[EE];
    const float4* er = reinterpret_cast<const float4*>(emb + (size_t)idx * EE);
    #pragma unroll
    for (int i = 0; i < 8; i++) {
        float4 v = er[i];
        ev[4 * i] = v.x; ev[4 * i + 1] = v.y; ev[4 * i + 2] = v.z; ev[4 * i + 3] = v.w;
    }

    const float* zrow = g_z + (size_t)n * EE;
    float* dwr = g_dw + (size_t)idx * EE;
    float sq = 0.0f;
    #pragma unroll
    for (int e = 0; e < EE; e++) {
        float zv = zrow[e];
        float d = ev[e] - zv;
        sq = fmaf(d, d, sq);
        atomicAdd(&dwr[e], zv);
    }
    atomicAdd(&g_counts[idx], 1.0f);

    float* ob = out + OFF_ZQ + (size_t)b * EE * HWW + p;
    #pragma unroll
    for (int e = 0; e < EE; e++) ob[(size_t)e * HWW] = ev[e];

    out[OFF_IDX + n] = (float)idx;

    __shared__ float red[256];
    red[t] = sq;
    __syncthreads();
    #pragma unroll
    for (int s = 128; s; s >>= 1) {
        if (t < s) red[t] += red[t + s];
        __syncthreads();
    }
    if (t == 0) atomicAdd(&g_qsum, red[0]);
}

__global__ __launch_bounds__(256) void ema1_kernel(const float* __restrict__ ema_cs, float* __restrict__ out) {
    const int t = threadIdx.x;
    const int k = blockIdx.x * 256 + t;
    float c = DECAY * ema_cs[k] + ONE_MINUS_DECAY * g_counts[k];
    out[OFF_CS + k] = c;
    __shared__ float red[256];
    red[t] = c;
    __syncthreads();
    #pragma unroll
    for (int s = 128; s; s >>= 1) {
        if (t < s) red[t] += red[t + s];
        __syncthreads();
    }
    if (t == 0) atomicAdd(&g_nsum, red[0]);
}

__global__ __launch_bounds__(256) void ema2_kernel(const float* __restrict__ ema_w, float* __restrict__ out) {
    const int i = blockIdx.x * 256 + threadIdx.x;
    const int k = i >> 5;
    float w = DECAY * ema_w[i] + ONE_MINUS_DECAY * g_dw[i];
    out[OFF_W + i] = w;
    float nt = g_nsum;
    float c = out[OFF_CS + k];
    float cs = (c + EPSI) / (nt + (float)KK * EPSI) * nt;
    out[OFF_EMB + i] = w / cs;
    if (i == 0) out[OFF_QL] = BETA * g_qsum / (float)(NN * EE);
}

extern "C" void kernel_launch(void* const* d_in, const int* in_sizes, int n_in,
                              void* d_out, int out_size) {
    const float* x   = (const float*)d_in[0];
    const float* Wq  = (const float*)d_in[1];
    const float* bq  = (const float*)d_in[2];
    const float* emb = (const float*)d_in[3];
    const float* ecs = (const float*)d_in[4];
    const float* ew  = (const float*)d_in[5];
    float* out = (float*)d_out;

    cudaFuncSetAttribute(argmax_hmma_kernel, cudaFuncAttributeMaxDynamicSharedMemorySize, SMEM_TOTAL);

    zero_kernel<<<264, 512>>>();
    proj_kernel<<<NN / 16, 256>>>(x, Wq, bq);
    inorm_kernel<<<KK / 8, 256>>>(emb);
    pack_bh_kernel<<<KK / 16, 256>>>(emb);
    argmax_hmma_kernel<<<256, 256, SMEM_TOTAL>>>();
    gather_kernel<<<NN / 256, 256>>>(emb, out);
    ema1_kernel<<<KK / 256, 256>>>(ecs, out);
    ema2_kernel<<<(KK * EE) / 256, 256>>>(ew, out);
}

// round 12
// speedup vs baseline: 1.4939x; 1.1597x over previous
#include <cuda_runtime.h>
#include <cuda_fp16.h>
#include <cstdint>
#include <cfloat>

#define CC 256
#define EE 32
#define KK 8192
#define NN 32768
#define HWW 4096
#define NT2 128          // tiles of 64 codes

#define DECAY 0.99f
#define ONE_MINUS_DECAY 0.01f
#define EPSI 1e-5f
#define BETA 0.25f

#define OFF_ZQ   0
#define OFF_IDX  1048576
#define OFF_QL   1081344
#define OFF_EMB  1081345
#define OFF_CS   1343489
#define OFF_W    1351681

// Scratch (device globals)
__device__ float g_z[NN * EE];                    // fp32 z_flat
__device__ __align__(16) __half g_bh[KK * 128];   // 2MB: per code row, 128 f16 = [eh|eh|el|el]
__device__ float g_inorm[KK];
__device__ float g_counts[KK];
__device__ float g_dw[KK * EE];
__device__ int   g_bidx[NN];
__device__ float g_qsum;
__device__ float g_nsum;

// ---------------- helpers ----------------
__device__ __forceinline__ uint32_t smem_u32(const void* p) {
    uint32_t a;
    asm("{ .reg .u64 t; cvta.to.shared.u64 t, %1; cvt.u32.u64 %0, t; }" : "=r"(a) : "l"(p));
    return a;
}
__device__ __forceinline__ void cp_async16(uint32_t saddr, const void* gaddr) {
    asm volatile("cp.async.cg.shared.global [%0], [%1], 16;" :: "r"(saddr), "l"(gaddr) : "memory");
}
__device__ __forceinline__ void mma16816(float* c, const uint32_t* a, const uint32_t* b) {
    asm volatile("mma.sync.aligned.m16n8k16.row.col.f32.f16.f16.f32 "
        "{%0,%1,%2,%3}, {%4,%5,%6,%7}, {%8,%9}, {%0,%1,%2,%3};"
        : "+f"(c[0]), "+f"(c[1]), "+f"(c[2]), "+f"(c[3])
        : "r"(a[0]), "r"(a[1]), "r"(a[2]), "r"(a[3]), "r"(b[0]), "r"(b[1]));
}
__device__ __forceinline__ void ldsm4(uint32_t* r, uint32_t addr) {
    asm volatile("ldmatrix.sync.aligned.m8n8.x4.shared.b16 {%0,%1,%2,%3}, [%4];"
        : "=r"(r[0]), "=r"(r[1]), "=r"(r[2]), "=r"(r[3]) : "r"(addr));
}
__device__ __forceinline__ void ldsm2(uint32_t* r, uint32_t addr) {
    asm volatile("ldmatrix.sync.aligned.m8n8.x2.shared.b16 {%0,%1}, [%2];"
        : "=r"(r[0]), "=r"(r[1]) : "r"(addr));
}
// XOR swizzle: rows of 256B, permute 16B chunks within each 128B half by row&7
__device__ __forceinline__ int swz(int row, int byte_) {
    int c8 = byte_ >> 4;
    int c8s = (c8 & 8) | ((c8 ^ row) & 7);
    return row * 256 + (c8s << 4) + (byte_ & 15);
}

// ---------------- zero ----------------
__global__ void zero_kernel() {
    int i = blockIdx.x * blockDim.x + threadIdx.x;
    int stride = gridDim.x * blockDim.x;
    for (int j = i; j < KK * EE; j += stride) g_dw[j] = 0.0f;
    for (int j = i; j < KK; j += stride) g_counts[j] = 0.0f;
    if (i == 0) { g_qsum = 0.0f; g_nsum = 0.0f; }
}

// ---------------- 1x1 conv ----------------
__global__ __launch_bounds__(256) void proj_kernel(
    const float* __restrict__ x, const float* __restrict__ Wq, const float* __restrict__ bq)
{
    __shared__ float sW[EE * CC];
    __shared__ float sx[CC * 16];
    const int t = threadIdx.x;
    const int n0 = blockIdx.x * 16;
    const int b = n0 >> 12;
    const int p0 = n0 & (HWW - 1);

    for (int i = t; i < EE * CC; i += 256) sW[i] = Wq[i];
    const float* xb = x + (size_t)b * CC * HWW + p0;
    #pragma unroll
    for (int j = 0; j < 16; j++) {
        int idx = j * 256 + t;
        int c = idx >> 4, pix = idx & 15;
        sx[idx] = xb[c * HWW + pix];
    }
    __syncthreads();

    const int pix = t & 15;
    const int e0 = (t >> 4) << 1;
    float a0 = 0.0f, a1 = 0.0f;
    #pragma unroll 8
    for (int c = 0; c < CC; c++) {
        float xv = sx[c * 16 + pix];
        a0 = fmaf(xv, sW[(e0 + 0) * CC + c], a0);
        a1 = fmaf(xv, sW[(e0 + 1) * CC + c], a1);
    }
    float* zr = g_z + (size_t)(n0 + pix) * EE + e0;
    zr[0] = a0 + bq[e0];
    zr[1] = a1 + bq[e0 + 1];
}

// ---------------- embedding inverse norms (scaled by 256) ----------------
__global__ __launch_bounds__(256) void inorm_kernel(const float* __restrict__ emb) {
    int k = blockIdx.x * 8 + (threadIdx.x >> 5);
    int e = threadIdx.x & 31;
    float v = emb[k * EE + e];
    float s = v * v;
    #pragma unroll
    for (int o = 16; o; o >>= 1) s += __shfl_xor_sync(0xFFFFFFFFu, s, o);
    if (e == 0) g_inorm[k] = 256.0f / fmaxf(sqrtf(s), 1e-12f);
}

// ---------------- pack B: natural row-major [code][128] = [eh|eh|el|el] ----------------
__global__ __launch_bounds__(256) void pack_bh_kernel(const float* __restrict__ emb) {
    const int code = blockIdx.x * 16 + (threadIdx.x >> 4);
    const int e0 = (threadIdx.x & 15) * 2;
    const float inv = g_inorm[code];
    float v0 = emb[(size_t)code * EE + e0] * inv;
    float v1 = emb[(size_t)code * EE + e0 + 1] * inv;
    __half h0 = __float2half_rn(v0), h1 = __float2half_rn(v1);
    __half l0 = __float2half_rn(v0 - __half2float(h0));
    __half l1 = __float2half_rn(v1 - __half2float(h1));
    __half2 hh = __halves2half2(h0, h1);
    __half2 ll = __halves2half2(l0, l1);
    __half2* row = (__half2*)(g_bh + (size_t)code * 128);
    const int i2 = e0 >> 1;
    row[i2]      = hh;   // k in [0,32)
    row[i2 + 16] = hh;   // k in [32,64)
    row[i2 + 32] = ll;   // k in [64,96)
    row[i2 + 48] = ll;   // k in [96,128)
}

// ---------------- HMMA argmax: A-in-registers, 64-code tiles, smem scores ----------------
// 256 CTAs x 256 thr (8 warps, 4m x 2n). M=128 pixels/CTA, 128 tiles of 64 codes, K=128.
// SMEM: A build 32KB @0 (idle after frag load), B double buffer 2x16KB @32768,
//       scores 128x68 fp32 @65536 (pitch 68 floats = 272B, 16B-aligned rows).
#define SC_PITCH 68
#define SM_B_OFF 32768
#define SM_SC_OFF 65536
#define SMEM_TOTAL (SM_SC_OFF + 128 * SC_PITCH * 4)   // 100352 -> 2 CTAs/SM

__global__ __launch_bounds__(256, 2) void argmax_hmma_kernel() {
    extern __shared__ __align__(16) char smem[];
    char* smA = smem;
    float* scores = (float*)(smem + SM_SC_OFF);
    const int t = threadIdx.x;
    const int l = t & 31, wid = t >> 5;
    const int wm = wid & 3, wn = wid >> 2;
    const int blk = blockIdx.x;
    const uint32_t sbA = smem_u32(smA);
    const uint32_t sbB = sbA + SM_B_OFF;

    // ---- build A tile in smem: pixel rows, K=128 = [zh|zl|zh|zl], swizzled ----
    {
        const int row = t >> 1;
        const int e0 = (t & 1) * 16;
        const float4* zr = (const float4*)(g_z + (size_t)(blk * 128 + row) * EE + e0);
        float zf[16];
        #pragma unroll
        for (int i = 0; i < 4; i++) {
            float4 v = zr[i];
            zf[4 * i] = v.x; zf[4 * i + 1] = v.y; zf[4 * i + 2] = v.z; zf[4 * i + 3] = v.w;
        }
        #pragma unroll
        for (int i = 0; i < 16; i += 2) {
            float v0 = 256.0f * zf[i];
            float v1 = 256.0f * zf[i + 1];
            __half h0 = __float2half_rn(v0), h1 = __float2half_rn(v1);
            __half l0 = __float2half_rn(v0 - __half2float(h0));
            __half l1 = __float2half_rn(v1 - __half2float(h1));
            __half2 hh = __halves2half2(h0, h1);
            __half2 ll = __halves2half2(l0, l1);
            const int b0 = 2 * (e0 + i);
            *(__half2*)(smA + swz(row, b0))       = hh;   // k = e
            *(__half2*)(smA + swz(row, b0 + 64))  = ll;   // k = e+32
            *(__half2*)(smA + swz(row, b0 + 128)) = hh;   // k = e+64
            *(__half2*)(smA + swz(row, b0 + 192)) = ll;   // k = e+96
        }
    }

    // ---- prologue: async-load B tile 0 while A settles ----
    {
        const uint4* src = (const uint4*)g_bh;
        #pragma unroll
        for (int i = 0; i < 4; i++) {
            int c = t + i * 256;
            int row = c >> 4, c8 = c & 15;
            int c8s = (c8 & 8) | ((c8 ^ row) & 7);
            cp_async16(sbB + row * 256 + (c8s << 4), src + c);
        }
        asm volatile("cp.async.commit_group;" ::: "memory");
    }

    __syncthreads();   // A build complete

    // ---- load A fragments into registers (once) ----
    const int arow0 = wm * 32 + (l & 15);
    const int abyte_lane = ((l >> 4) & 1) * 16;
    uint32_t afrag[8][8];   // [k-step][a0:0..3, a1:4..7]
    #pragma unroll
    for (int s = 0; s < 8; s++) {
        const int abyte = s * 32 + abyte_lane;
        ldsm4(&afrag[s][0], sbA + swz(arow0, abyte));
        ldsm4(&afrag[s][4], sbA + swz(arow0 + 16, abyte));
    }

    float best = -FLT_MAX;
    int bidx = 0;

    const int brow_lane = (l & 7);
    const int bbyte_lane = ((l >> 3) & 1) * 16;
    const float* srow = scores + (t >> 1) * SC_PITCH + (t & 1) * 32;

    for (int tt = 0; tt < NT2; tt++) {
        // prefetch tile tt+1 into the other buffer (MMA tt-1 done via tt-1's post-store sync)
        if (tt + 1 < NT2) {
            const uint4* src = (const uint4*)(g_bh + (size_t)(tt + 1) * 64 * 128);
            uint32_t dst = sbB + ((tt + 1) & 1) * 16384;
            #pragma unroll
            for (int i = 0; i < 4; i++) {
                int c = t + i * 256;
                int row = c >> 4, c8 = c & 15;
                int c8s = (c8 & 8) | ((c8 ^ row) & 7);
                cp_async16(dst + row * 256 + (c8s << 4), src + c);
            }
        }
        asm volatile("cp.async.commit_group;" ::: "memory");
        asm volatile("cp.async.wait_group 1;" ::: "memory");   // B(tt) complete
        __syncthreads();   // B(tt) visible; scan(tt-1) done before store(tt)

        const uint32_t sB = sbB + (tt & 1) * 16384;

        // ---- compute 128x64 scores ----
        float c_[2][4][4];
        #pragma unroll
        for (int mi = 0; mi < 2; mi++)
            #pragma unroll
            for (int j = 0; j < 4; j++)
                #pragma unroll
                for (int q = 0; q < 4; q++) c_[mi][j][q] = 0.0f;

        #pragma unroll
        for (int s = 0; s < 8; s++) {
            #pragma unroll
            for (int j = 0; j < 4; j++) {
                uint32_t b[2];
                const int brow = (wn * 4 + j) * 8 + brow_lane;
                ldsm2(b, sB + swz(brow, s * 32 + bbyte_lane));
                mma16816(c_[0][j], &afrag[s][0], b);
                mma16816(c_[1][j], &afrag[s][4], b);
            }
        }

        // ---- store C fragments to smem scores (validated mapping) ----
        #pragma unroll
        for (int mi = 0; mi < 2; mi++) {
            const int r0 = wm * 32 + mi * 16 + (l >> 2);
            #pragma unroll
            for (int j = 0; j < 4; j++) {
                const int col = wn * 32 + j * 8 + (l & 3) * 2;
                float* p0 = scores + r0 * SC_PITCH + col;
                float* p1 = scores + (r0 + 8) * SC_PITCH + col;
                p0[0] = c_[mi][j][0];
                p0[1] = c_[mi][j][1];
                p1[0] = c_[mi][j][2];
                p1[1] = c_[mi][j][3];
            }
        }
        __syncthreads();

        // ---- serial scan: ascending col, strict > ----
        const int cb = tt * 64 + (t & 1) * 32;
        #pragma unroll
        for (int c = 0; c < 32; c += 4) {
            float4 v = *(const float4*)(srow + c);
            if (v.x > best) { best = v.x; bidx = cb + c; }
            if (v.y > best) { best = v.y; bidx = cb + c + 1; }
            if (v.z > best) { best = v.z; bidx = cb + c + 2; }
            if (v.w > best) { best = v.w; bidx = cb + c + 3; }
        }
    }

    // merge the two column halves of each row
    {
        float ov = __shfl_xor_sync(0xFFFFFFFFu, best, 1);
        int oi = __shfl_xor_sync(0xFFFFFFFFu, bidx, 1);
        if (ov > best || (ov == best && oi < bidx)) { best = ov; bidx = oi; }
        if ((t & 1) == 0) g_bidx[blk * 128 + (t >> 1)] = bidx;
    }
}

// ---------------- gather + qloss + EMA scatter ----------------
__global__ __launch_bounds__(256) void gather_kernel(const float* __restrict__ emb, float* __restrict__ out) {
    const int t = threadIdx.x;
    const int n = blockIdx.x * 256 + t;
    const int idx = g_bidx[n];
    const int b = n >> 12, p = n & (HWW - 1);

    float ev[EE];
    const float4* er = reinterpret_cast<const float4*>(emb + (size_t)idx * EE);
    #pragma unroll
    for (int i = 0; i < 8; i++) {
        float4 v = er[i];
        ev[4 * i] = v.x; ev[4 * i + 1] = v.y; ev[4 * i + 2] = v.z; ev[4 * i + 3] = v.w;
    }

    const float* zrow = g_z + (size_t)n * EE;
    float* dwr = g_dw + (size_t)idx * EE;
    float sq = 0.0f;
    #pragma unroll
    for (int e = 0; e < EE; e++) {
        float zv = zrow[e];
        float d = ev[e] - zv;
        sq = fmaf(d, d, sq);
        atomicAdd(&dwr[e], zv);
    }
    atomicAdd(&g_counts[idx], 1.0f);

    float* ob = out + OFF_ZQ + (size_t)b * EE * HWW + p;
    #pragma unroll
    for (int e = 0; e < EE; e++) ob[(size_t)e * HWW] = ev[e];

    out[OFF_IDX + n] = (float)idx;

    __shared__ float red[256];
    red[t] = sq;
    __syncthreads();
    #pragma unroll
    for (int s = 128; s; s >>= 1) {
        if (t < s) red[t] += red[t + s];
        __syncthreads();
    }
    if (t == 0) atomicAdd(&g_qsum, red[0]);
}

__global__ __launch_bounds__(256) void ema1_kernel(const float* __restrict__ ema_cs, float* __restrict__ out) {
    const int t = threadIdx.x;
    const int k = blockIdx.x * 256 + t;
    float c = DECAY * ema_cs[k] + ONE_MINUS_DECAY * g_counts[k];
    out[OFF_CS + k] = c;
    __shared__ float red[256];
    red[t] = c;
    __syncthreads();
    #pragma unroll
    for (int s = 128; s; s >>= 1) {
        if (t < s) red[t] += red[t + s];
        __syncthreads();
    }
    if (t == 0) atomicAdd(&g_nsum, red[0]);
}

__global__ __launch_bounds__(256) void ema2_kernel(const float* __restrict__ ema_w, float* __restrict__ out) {
    const int i = blockIdx.x * 256 + threadIdx.x;
    const int k = i >> 5;
    float w = DECAY * ema_w[i] + ONE_MINUS_DECAY * g_dw[i];
    out[OFF_W + i] = w;
    float nt = g_nsum;
    float c = out[OFF_CS + k];
    float cs = (c + EPSI) / (nt + (float)KK * EPSI) * nt;
    out[OFF_EMB + i] = w / cs;
    if (i == 0) out[OFF_QL] = BETA * g_qsum / (float)(NN * EE);
}

extern "C" void kernel_launch(void* const* d_in, const int* in_sizes, int n_in,
                              void* d_out, int out_size) {
    const float* x   = (const float*)d_in[0];
    const float* Wq  = (const float*)d_in[1];
    const float* bq  = (const float*)d_in[2];
    const float* emb = (const float*)d_in[3];
    const float* ecs = (const float*)d_in[4];
    const float* ew  = (const float*)d_in[5];
    float* out = (float*)d_out;

    cudaFuncSetAttribute(argmax_hmma_kernel, cudaFuncAttributeMaxDynamicSharedMemorySize, SMEM_TOTAL);

    zero_kernel<<<264, 512>>>();
    proj_kernel<<<NN / 16, 256>>>(x, Wq, bq);
    inorm_kernel<<<KK / 8, 256>>>(emb);
    pack_bh_kernel<<<KK / 16, 256>>>(emb);
    argmax_hmma_kernel<<<256, 256, SMEM_TOTAL>>>();
    gather_kernel<<<NN / 256, 256>>>(emb, out);
    ema1_kernel<<<KK / 256, 256>>>(ecs, out);
    ema2_kernel<<<(KK * EE) / 256, 256>>>(ew, out);
}

// round 14
// speedup vs baseline: 1.9230x; 1.2872x over previous
#include <cuda_runtime.h>
#include <cuda_fp16.h>
#include <cstdint>
#include <cfloat>

#define CC 256
#define EE 32
#define KK 8192
#define NN 32768
#define HWW 4096
#define NT2 128          // tiles of 64 codes

#define DECAY 0.99f
#define ONE_MINUS_DECAY 0.01f
#define EPSI 1e-5f
#define BETA 0.25f

#define OFF_ZQ   0
#define OFF_IDX  1048576
#define OFF_QL   1081344
#define OFF_EMB  1081345
#define OFF_CS   1343489
#define OFF_W    1351681

// Scratch (device globals)
__device__ float g_z[NN * EE];                    // fp32 z_flat
__device__ __align__(16) __half g_bh[KK * 128];   // 2MB: per code row, 128 f16 = [eh|eh|el|el]
__device__ float g_inorm[KK];
__device__ float g_counts[KK];
__device__ float g_dw[KK * EE];
__device__ int   g_bidx[NN];
__device__ float g_qsum;
__device__ float g_nsum;

// ---------------- helpers ----------------
__device__ __forceinline__ uint32_t smem_u32(const void* p) {
    uint32_t a;
    asm("{ .reg .u64 t; cvta.to.shared.u64 t, %1; cvt.u32.u64 %0, t; }" : "=r"(a) : "l"(p));
    return a;
}
__device__ __forceinline__ void cp_async16(uint32_t saddr, const void* gaddr) {
    asm volatile("cp.async.cg.shared.global [%0], [%1], 16;" :: "r"(saddr), "l"(gaddr) : "memory");
}
__device__ __forceinline__ void mma16816(float* c, const uint32_t* a, const uint32_t* b) {
    asm volatile("mma.sync.aligned.m16n8k16.row.col.f32.f16.f16.f32 "
        "{%0,%1,%2,%3}, {%4,%5,%6,%7}, {%8,%9}, {%0,%1,%2,%3};"
        : "+f"(c[0]), "+f"(c[1]), "+f"(c[2]), "+f"(c[3])
        : "r"(a[0]), "r"(a[1]), "r"(a[2]), "r"(a[3]), "r"(b[0]), "r"(b[1]));
}
__device__ __forceinline__ void ldsm4(uint32_t* r, uint32_t addr) {
    asm volatile("ldmatrix.sync.aligned.m8n8.x4.shared.b16 {%0,%1,%2,%3}, [%4];"
        : "=r"(r[0]), "=r"(r[1]), "=r"(r[2]), "=r"(r[3]) : "r"(addr));
}
__device__ __forceinline__ void ldsm2(uint32_t* r, uint32_t addr) {
    asm volatile("ldmatrix.sync.aligned.m8n8.x2.shared.b16 {%0,%1}, [%2];"
        : "=r"(r[0]), "=r"(r[1]) : "r"(addr));
}
// XOR swizzle: rows of 256B, permute 16B chunks within each 128B half by row&7
__device__ __forceinline__ int swz(int row, int byte_) {
    int c8 = byte_ >> 4;
    int c8s = (c8 & 8) | ((c8 ^ row) & 7);
    return row * 256 + (c8s << 4) + (byte_ & 15);
}

// ---------------- zero ----------------
__global__ void zero_kernel() {
    int i = blockIdx.x * blockDim.x + threadIdx.x;
    int stride = gridDim.x * blockDim.x;
    for (int j = i; j < KK * EE; j += stride) g_dw[j] = 0.0f;
    for (int j = i; j < KK; j += stride) g_counts[j] = 0.0f;
    if (i == 0) { g_qsum = 0.0f; g_nsum = 0.0f; }
}

// ---------------- 1x1 conv ----------------
__global__ __launch_bounds__(256) void proj_kernel(
    const float* __restrict__ x, const float* __restrict__ Wq, const float* __restrict__ bq)
{
    __shared__ float sW[EE * CC];
    __shared__ float sx[CC * 16];
    const int t = threadIdx.x;
    const int n0 = blockIdx.x * 16;
    const int b = n0 >> 12;
    const int p0 = n0 & (HWW - 1);

    for (int i = t; i < EE * CC; i += 256) sW[i] = Wq[i];
    const float* xb = x + (size_t)b * CC * HWW + p0;
    #pragma unroll
    for (int j = 0; j < 16; j++) {
        int idx = j * 256 + t;
        int c = idx >> 4, pix = idx & 15;
        sx[idx] = xb[c * HWW + pix];
    }
    __syncthreads();

    const int pix = t & 15;
    const int e0 = (t >> 4) << 1;
    float a0 = 0.0f, a1 = 0.0f;
    #pragma unroll 8
    for (int c = 0; c < CC; c++) {
        float xv = sx[c * 16 + pix];
        a0 = fmaf(xv, sW[(e0 + 0) * CC + c], a0);
        a1 = fmaf(xv, sW[(e0 + 1) * CC + c], a1);
    }
    float* zr = g_z + (size_t)(n0 + pix) * EE + e0;
    zr[0] = a0 + bq[e0];
    zr[1] = a1 + bq[e0 + 1];
}

// ---------------- embedding inverse norms (scaled by 256) ----------------
__global__ __launch_bounds__(256) void inorm_kernel(const float* __restrict__ emb) {
    int k = blockIdx.x * 8 + (threadIdx.x >> 5);
    int e = threadIdx.x & 31;
    float v = emb[k * EE + e];
    float s = v * v;
    #pragma unroll
    for (int o = 16; o; o >>= 1) s += __shfl_xor_sync(0xFFFFFFFFu, s, o);
    if (e == 0) g_inorm[k] = 256.0f / fmaxf(sqrtf(s), 1e-12f);
}

// ---------------- pack B: natural row-major [code][128] = [eh|eh|el|el] ----------------
__global__ __launch_bounds__(256) void pack_bh_kernel(const float* __restrict__ emb) {
    const int code = blockIdx.x * 16 + (threadIdx.x >> 4);
    const int e0 = (threadIdx.x & 15) * 2;
    const float inv = g_inorm[code];
    float v0 = emb[(size_t)code * EE + e0] * inv;
    float v1 = emb[(size_t)code * EE + e0 + 1] * inv;
    __half h0 = __float2half_rn(v0), h1 = __float2half_rn(v1);
    __half l0 = __float2half_rn(v0 - __half2float(h0));
    __half l1 = __float2half_rn(v1 - __half2float(h1));
    __half2 hh = __halves2half2(h0, h1);
    __half2 ll = __halves2half2(l0, l1);
    __half2* row = (__half2*)(g_bh + (size_t)code * 128);
    const int i2 = e0 >> 1;
    row[i2]      = hh;   // k in [0,32)
    row[i2 + 16] = hh;   // k in [32,64)
    row[i2 + 32] = ll;   // k in [64,96)
    row[i2 + 48] = ll;   // k in [96,128)
}

// ---------------- HMMA argmax: A-in-registers, register argmax + cross-warp merge ----------------
// 256 CTAs x 256 thr (8 warps, 4m x 2n). M=128 pixels/CTA, 128 tiles of 64 codes, K=128.
// SMEM: A build 32KB @0 (reused: merge buffer after frag load), B double buffer 2x16KB @32768.
#define SM_B_OFF 32768
#define SMEM_TOTAL (SM_B_OFF + 32768)

__global__ __launch_bounds__(256, 2) void argmax_hmma_kernel() {
    extern __shared__ __align__(16) char smem[];
    char* smA = smem;
    const int t = threadIdx.x;
    const int l = t & 31, wid = t >> 5;
    const int wm = wid & 3, wn = wid >> 2;
    const int blk = blockIdx.x;
    const uint32_t sbA = smem_u32(smA);
    const uint32_t sbB = sbA + SM_B_OFF;

    // ---- build A tile in smem: pixel rows, K=128 = [zh|zl|zh|zl], swizzled ----
    {
        const int row = t >> 1;
        const int e0 = (t & 1) * 16;
        const float4* zr = (const float4*)(g_z + (size_t)(blk * 128 + row) * EE + e0);
        float zf[16];
        #pragma unroll
        for (int i = 0; i < 4; i++) {
            float4 v = zr[i];
            zf[4 * i] = v.x; zf[4 * i + 1] = v.y; zf[4 * i + 2] = v.z; zf[4 * i + 3] = v.w;
        }
        #pragma unroll
        for (int i = 0; i < 16; i += 2) {
            float v0 = 256.0f * zf[i];
            float v1 = 256.0f * zf[i + 1];
            __half h0 = __float2half_rn(v0), h1 = __float2half_rn(v1);
            __half l0 = __float2half_rn(v0 - __half2float(h0));
            __half l1 = __float2half_rn(v1 - __half2float(h1));
            __half2 hh = __halves2half2(h0, h1);
            __half2 ll = __halves2half2(l0, l1);
            const int b0 = 2 * (e0 + i);
            *(__half2*)(smA + swz(row, b0))       = hh;   // k = e
            *(__half2*)(smA + swz(row, b0 + 64))  = ll;   // k = e+32
            *(__half2*)(smA + swz(row, b0 + 128)) = hh;   // k = e+64
            *(__half2*)(smA + swz(row, b0 + 192)) = ll;   // k = e+96
        }
    }

    // ---- prologue: async-load B tile 0 while A settles ----
    {
        const uint4* src = (const uint4*)g_bh;
        #pragma unroll
        for (int i = 0; i < 4; i++) {
            int c = t + i * 256;
            int row = c >> 4, c8 = c & 15;
            int c8s = (c8 & 8) | ((c8 ^ row) & 7);
            cp_async16(sbB + row * 256 + (c8s << 4), src + c);
        }
        asm volatile("cp.async.commit_group;" ::: "memory");
    }

    __syncthreads();   // A build complete

    // ---- load A fragments into registers (once) ----
    const int arow0 = wm * 32 + (l & 15);
    const int abyte_lane = ((l >> 4) & 1) * 16;
    uint32_t afrag[8][8];   // [k-step][a0:0..3, a1:4..7]
    #pragma unroll
    for (int s = 0; s < 8; s++) {
        const int abyte = s * 32 + abyte_lane;
        ldsm4(&afrag[s][0], sbA + swz(arow0, abyte));
        ldsm4(&afrag[s][4], sbA + swz(arow0 + 16, abyte));
    }

    // per-thread running argmax over this warp's half-columns:
    // 4 row-slots (mi*2+h -> row wm*32+mi*16+h*8+(l>>2))
    float best[4] = {-FLT_MAX, -FLT_MAX, -FLT_MAX, -FLT_MAX};
    int bidx[4] = {0, 0, 0, 0};

    const int brow_lane = (l & 7);
    const int bbyte_lane = ((l >> 3) & 1) * 16;

    for (int tt = 0; tt < NT2; tt++) {
        // prefetch tile tt+1 into the other buffer
        if (tt + 1 < NT2) {
            const uint4* src = (const uint4*)(g_bh + (size_t)(tt + 1) * 64 * 128);
            uint32_t dst = sbB + ((tt + 1) & 1) * 16384;
            #pragma unroll
            for (int i = 0; i < 4; i++) {
                int c = t + i * 256;
                int row = c >> 4, c8 = c & 15;
                int c8s = (c8 & 8) | ((c8 ^ row) & 7);
                cp_async16(dst + row * 256 + (c8s << 4), src + c);
            }
        }
        asm volatile("cp.async.commit_group;" ::: "memory");
        asm volatile("cp.async.wait_group 1;" ::: "memory");   // B(tt) complete
        __syncthreads();   // B(tt) visible to all warps

        const uint32_t sB = sbB + (tt & 1) * 16384;

        // ---- compute 128x64 scores ----
        float c_[2][4][4];
        #pragma unroll
        for (int mi = 0; mi < 2; mi++)
            #pragma unroll
            for (int j = 0; j < 4; j++)
                #pragma unroll
                for (int q = 0; q < 4; q++) c_[mi][j][q] = 0.0f;

        #pragma unroll
        for (int s = 0; s < 8; s++) {
            #pragma unroll
            for (int j = 0; j < 4; j++) {
                uint32_t b[2];
                const int brow = (wn * 4 + j) * 8 + brow_lane;
                ldsm2(b, sB + swz(brow, s * 32 + bbyte_lane));
                mma16816(c_[0][j], &afrag[s][0], b);
                mma16816(c_[1][j], &afrag[s][4], b);
            }
        }

        // ---- register argmax (ascending column order, strict >, explicit indices)
        //      Mapping validated via R9/R12 store path.
        const int colbase = tt * 64 + wn * 32 + (l & 3) * 2;
        #pragma unroll
        for (int mi = 0; mi < 2; mi++) {
            const int s0 = mi * 2;
            #pragma unroll
            for (int j = 0; j < 4; j++) {
                const int c0 = colbase + j * 8;
                if (c_[mi][j][0] > best[s0])     { best[s0] = c_[mi][j][0];     bidx[s0] = c0; }
                if (c_[mi][j][1] > best[s0])     { best[s0] = c_[mi][j][1];     bidx[s0] = c0 + 1; }
                if (c_[mi][j][2] > best[s0 + 1]) { best[s0 + 1] = c_[mi][j][2]; bidx[s0 + 1] = c0; }
                if (c_[mi][j][3] > best[s0 + 1]) { best[s0 + 1] = c_[mi][j][3]; bidx[s0 + 1] = c0 + 1; }
            }
        }
        __syncthreads();   // all warps done reading B(tt) before overwrite (tt+2)
    }

    // ---- quad reduce within warp, then cross-wn merge via smem ----
    // (THE FIX: warps (wm,0) and (wm,1) cover different column halves of the
    //  SAME rows; previous register versions raced on g_bidx here.)
    float* mbest = (float*)smA;              // [2][128]
    int*   midx  = (int*)(smA + 1024);       // [2][128]
    #pragma unroll
    for (int slot = 0; slot < 4; slot++) {
        float v = best[slot];
        int i = bidx[slot];
        #pragma unroll
        for (int o = 1; o <= 2; o <<= 1) {
            float ov = __shfl_xor_sync(0xFFFFFFFFu, v, o);
            int oi = __shfl_xor_sync(0xFFFFFFFFu, i, o);
            if (ov > v || (ov == v && oi < i)) { v = ov; i = oi; }
        }
        if ((l & 3) == 0) {
            const int mi = slot >> 1, h = slot & 1;
            const int row = wm * 32 + mi * 16 + h * 8 + (l >> 2);
            mbest[wn * 128 + row] = v;
            midx[wn * 128 + row] = i;
        }
    }
    __syncthreads();
    if (t < 128) {
        float v0 = mbest[t], v1 = mbest[128 + t];
        int i0 = midx[t], i1 = midx[128 + t];
        // global smaller-index tie-break == jnp.argmax first-max
        bool p = (v1 > v0) || (v1 == v0 && i1 < i0);
        g_bidx[blk * 128 + t] = p ? i1 : i0;
    }
}

// ---------------- gather + qloss + EMA scatter ----------------
__global__ __launch_bounds__(256) void gather_kernel(const float* __restrict__ emb, float* __restrict__ out) {
    const int t = threadIdx.x;
    const int n = blockIdx.x * 256 + t;
    const int idx = g_bidx[n];
    const int b = n >> 12, p = n & (HWW - 1);

    float ev[EE];
    const float4* er = reinterpret_cast<const float4*>(emb + (size_t)idx * EE);
    #pragma unroll
    for (int i = 0; i < 8; i++) {
        float4 v = er[i];
        ev[4 * i] = v.x; ev[4 * i + 1] = v.y; ev[4 * i + 2] = v.z; ev[4 * i + 3] = v.w;
    }

    const float* zrow = g_z + (size_t)n * EE;
    float* dwr = g_dw + (size_t)idx * EE;
    float sq = 0.0f;
    #pragma unroll
    for (int e = 0; e < EE; e++) {
        float zv = zrow[e];
        float d = ev[e] - zv;
        sq = fmaf(d, d, sq);
        atomicAdd(&dwr[e], zv);
    }
    atomicAdd(&g_counts[idx], 1.0f);

    float* ob = out + OFF_ZQ + (size_t)b * EE * HWW + p;
    #pragma unroll
    for (int e = 0; e < EE; e++) ob[(size_t)e * HWW] = ev[e];

    out[OFF_IDX + n] = (float)idx;

    __shared__ float red[256];
    red[t] = sq;
    __syncthreads();
    #pragma unroll
    for (int s = 128; s; s >>= 1) {
        if (t < s) red[t] += red[t + s];
        __syncthreads();
    }
    if (t == 0) atomicAdd(&g_qsum, red[0]);
}

__global__ __launch_bounds__(256) void ema1_kernel(const float* __restrict__ ema_cs, float* __restrict__ out) {
    const int t = threadIdx.x;
    const int k = blockIdx.x * 256 + t;
    float c = DECAY * ema_cs[k] + ONE_MINUS_DECAY * g_counts[k];
    out[OFF_CS + k] = c;
    __shared__ float red[256];
    red[t] = c;
    __syncthreads();
    #pragma unroll
    for (int s = 128; s; s >>= 1) {
        if (t < s) red[t] += red[t + s];
        __syncthreads();
    }
    if (t == 0) atomicAdd(&g_nsum, red[0]);
}

__global__ __launch_bounds__(256) void ema2_kernel(const float* __restrict__ ema_w, float* __restrict__ out) {
    const int i = blockIdx.x * 256 + threadIdx.x;
    const int k = i >> 5;
    float w = DECAY * ema_w[i] + ONE_MINUS_DECAY * g_dw[i];
    out[OFF_W + i] = w;
    float nt = g_nsum;
    float c = out[OFF_CS + k];
    float cs = (c + EPSI) / (nt + (float)KK * EPSI) * nt;
    out[OFF_EMB + i] = w / cs;
    if (i == 0) out[OFF_QL] = BETA * g_qsum / (float)(NN * EE);
}

extern "C" void kernel_launch(void* const* d_in, const int* in_sizes, int n_in,
                              void* d_out, int out_size) {
    const float* x   = (const float*)d_in[0];
    const float* Wq  = (const float*)d_in[1];
    const float* bq  = (const float*)d_in[2];
    const float* emb = (const float*)d_in[3];
    const float* ecs = (const float*)d_in[4];
    const float* ew  = (const float*)d_in[5];
    float* out = (float*)d_out;

    cudaFuncSetAttribute(argmax_hmma_kernel, cudaFuncAttributeMaxDynamicSharedMemorySize, SMEM_TOTAL);

    zero_kernel<<<264, 512>>>();
    proj_kernel<<<NN / 16, 256>>>(x, Wq, bq);
    inorm_kernel<<<KK / 8, 256>>>(emb);
    pack_bh_kernel<<<KK / 16, 256>>>(emb);
    argmax_hmma_kernel<<<256, 256, SMEM_TOTAL>>>();
    gather_kernel<<<NN / 256, 256>>>(emb, out);
    ema1_kernel<<<KK / 256, 256>>>(ecs, out);
    ema2_kernel<<<(KK * EE) / 256, 256>>>(ew, out);
}